// round 15
// baseline (speedup 1.0000x reference)
#include <cuda_runtime.h>
#include <cstdint>
#include <math.h>

// Problem constants (B=8, SQ=SK=4096, D=64)
#define B_   8
#define SQ_  4096
#define SK_  4096
#define D_   64

#define BQ   128
#define BK   64
#define NT_  (SK_ / BK)   // 64 tiles
#define NTHREADS 256
#define KBSTRIDE  72      // bf16 K plane smem row stride (u32)
#define VSTRIDE   40      // V fp16 plane smem dim-row stride (u32)

#define KB_U32      (BK * KBSTRIDE)               // 4608 per buffer (x2)
#define V_U32       (D_ * VSTRIDE)                // 2560 per buffer (x3)
#define SMEM_U32    (2 * KB_U32 + 3 * V_U32)      // 16896
#define SMEM_BYTES  (SMEM_U32 * 4)                // 67584 -> 2 CTAs/SM

#define ONES_F16X2  0x3C003C00u                   // fp16 {1.0, 1.0}

// pre-converted K/V planes in the exact per-tile smem layout
__device__ uint32_t g_KB[B_][NT_][BK][64];   // 8 MB
__device__ uint32_t g_VP[B_][NT_][D_][32];   // 4 MB

__device__ __forceinline__ float fast_exp2(float x) {
    float y; asm("ex2.approx.ftz.f32 %0, %1;" : "=f"(y) : "f"(x)); return y;
}
__device__ __forceinline__ uint32_t exp2_f16x2(uint32_t x) {
    uint32_t y; asm("ex2.approx.f16x2 %0, %1;" : "=r"(y) : "r"(x)); return y;
}
__device__ __forceinline__ uint32_t pack_bf16_hi(float f0, float f1, float& r0, float& r1) {
    uint32_t u;
    asm("cvt.rn.bf16x2.f32 %0, %1, %2;" : "=r"(u) : "f"(f1), "f"(f0));
    r0 = f0 - __uint_as_float(u << 16);
    r1 = f1 - __uint_as_float(u & 0xffff0000u);
    return u;
}
__device__ __forceinline__ uint32_t pack_bf16(float f0, float f1) {
    uint32_t u;
    asm("cvt.rn.bf16x2.f32 %0, %1, %2;" : "=r"(u) : "f"(f1), "f"(f0));
    return u;
}
__device__ __forceinline__ uint32_t pack_f16(float f0, float f1) {
    uint32_t u;
    asm("cvt.rn.f16x2.f32 %0, %1, %2;" : "=r"(u) : "f"(f1), "f"(f0));
    return u;
}

__device__ __forceinline__ void mma_bf16(float& d0, float& d1, float& d2, float& d3,
                                         uint32_t a0, uint32_t a1, uint32_t a2, uint32_t a3,
                                         uint32_t b0, uint32_t b1) {
    asm volatile(
        "mma.sync.aligned.m16n8k16.row.col.f32.bf16.bf16.f32 "
        "{%0,%1,%2,%3}, {%4,%5,%6,%7}, {%8,%9}, {%0,%1,%2,%3};"
        : "+f"(d0), "+f"(d1), "+f"(d2), "+f"(d3)
        : "r"(a0), "r"(a1), "r"(a2), "r"(a3), "r"(b0), "r"(b1));
}
__device__ __forceinline__ void mma_f16(float& d0, float& d1, float& d2, float& d3,
                                        uint32_t a0, uint32_t a1, uint32_t a2, uint32_t a3,
                                        uint32_t b0, uint32_t b1) {
    asm volatile(
        "mma.sync.aligned.m16n8k16.row.col.f32.f16.f16.f32 "
        "{%0,%1,%2,%3}, {%4,%5,%6,%7}, {%8,%9}, {%0,%1,%2,%3};"
        : "+f"(d0), "+f"(d1), "+f"(d2), "+f"(d3)
        : "r"(a0), "r"(a1), "r"(a2), "r"(a3), "r"(b0), "r"(b1));
}

__device__ __forceinline__ void cp_async16(uint32_t dst, const void* src) {
    asm volatile("cp.async.cg.shared.global [%0], [%1], 16;" :: "r"(dst), "l"(src));
}

// ================= pre-pass: fp32 K/V -> packed planes (gmem) =================
__global__ void __launch_bounds__(256)
fa_preconv_kernel(const float* __restrict__ K, const float* __restrict__ V)
{
    const int tile = blockIdx.x;
    const int b    = blockIdx.y;
    const int tid  = threadIdx.x;

    // ---- K: thread = (key row, 16-dim chunk) ----
    {
        const int kkey = tid >> 2, kdc = tid & 3;
        const float* ksrc = K + (((size_t)b * SK_) + tile * BK + kkey) * D_ + kdc * 16;
        float4 v0 = __ldg(reinterpret_cast<const float4*>(ksrc));
        float4 v1 = __ldg(reinterpret_cast<const float4*>(ksrc + 4));
        float4 v2 = __ldg(reinterpret_cast<const float4*>(ksrc + 8));
        float4 v3 = __ldg(reinterpret_cast<const float4*>(ksrc + 12));
        float r[16];
        uint32_t hi[8], lo[8];
        hi[0] = pack_bf16_hi(v0.x, v0.y, r[0], r[1]);
        hi[1] = pack_bf16_hi(v0.z, v0.w, r[2], r[3]);
        hi[2] = pack_bf16_hi(v1.x, v1.y, r[4], r[5]);
        hi[3] = pack_bf16_hi(v1.z, v1.w, r[6], r[7]);
        hi[4] = pack_bf16_hi(v2.x, v2.y, r[8], r[9]);
        hi[5] = pack_bf16_hi(v2.z, v2.w, r[10], r[11]);
        hi[6] = pack_bf16_hi(v3.x, v3.y, r[12], r[13]);
        hi[7] = pack_bf16_hi(v3.z, v3.w, r[14], r[15]);
        #pragma unroll
        for (int j = 0; j < 8; ++j) lo[j] = pack_bf16(r[2 * j], r[2 * j + 1]);
        uint32_t* kdst = &g_KB[b][tile][kkey][kdc * 8];
        *reinterpret_cast<uint4*>(kdst)          = make_uint4(hi[0], hi[4], hi[1], hi[5]);
        *reinterpret_cast<uint4*>(kdst + 4)      = make_uint4(hi[2], hi[6], hi[3], hi[7]);
        *reinterpret_cast<uint4*>(kdst + 32)     = make_uint4(lo[0], lo[4], lo[1], lo[5]);
        *reinterpret_cast<uint4*>(kdst + 32 + 4) = make_uint4(lo[2], lo[6], lo[3], lo[7]);
    }
    // ---- V: thread = (key pair, 8-dim chunk), column-permuted fp16 ----
    {
        const int vkp = tid & 31, vdc = tid >> 5;
        const int vcol = (vkp & 24) | ((vkp & 3) << 1) | ((vkp >> 2) & 1);
        const float* s0 = V + (((size_t)b * SK_) + tile * BK + 2 * vkp) * D_ + vdc * 8;
        const float* s1 = s0 + D_;
        #pragma unroll
        for (int i = 0; i < 2; ++i) {
            float4 a = __ldg(reinterpret_cast<const float4*>(s0 + 4 * i));
            float4 c = __ldg(reinterpret_cast<const float4*>(s1 + 4 * i));
            float fa[4] = {a.x, a.y, a.z, a.w};
            float fc[4] = {c.x, c.y, c.z, c.w};
            #pragma unroll
            for (int j = 0; j < 4; ++j) {
                int d = vdc * 8 + 4 * i + j;
                g_VP[b][tile][d][vcol] = pack_f16(fa[j], fc[j]);
            }
        }
    }
}

// cp.async one tile's planes: K into kb (2-deep), V into vb (3-deep).
__device__ __forceinline__ void issue_planes(const uint32_t* __restrict__ KBg,
                                             const uint32_t* __restrict__ VPg,
                                             uint32_t* KBs, uint32_t* VPs, int tid) {
    #pragma unroll
    for (int i = 0; i < 4; ++i) {
        int slot = tid + i * NTHREADS;      // 1024 chunks of 16B
        int row = slot >> 4, c = slot & 15;
        uint32_t dst = (uint32_t)__cvta_generic_to_shared(KBs + row * KBSTRIDE + c * 4);
        cp_async16(dst, KBg + row * 64 + c * 4);
    }
    #pragma unroll
    for (int i = 0; i < 2; ++i) {
        int slot = tid + i * NTHREADS;      // 512 chunks of 16B
        int row = slot >> 3, c = slot & 7;
        uint32_t dst = (uint32_t)__cvta_generic_to_shared(VPs + row * VSTRIDE + c * 4);
        cp_async16(dst, VPg + row * 32 + c * 4);
    }
    asm volatile("cp.async.commit_group;");
}

__global__ void __launch_bounds__(NTHREADS, 2)
fa_main_kernel(const float* __restrict__ Q, const float* __restrict__ scale_div,
               float* __restrict__ O)
{
    extern __shared__ uint32_t smem[];
    uint32_t* KB0 = smem;                    // K planes: 2 buffers
    uint32_t* VP0 = smem + 2 * KB_U32;       // V planes: 3 buffers

    const int tid  = threadIdx.x;
    const int w    = tid >> 5;
    const int lane = tid & 31;
    const int g    = lane >> 2;   // 0..7
    const int tg   = lane & 3;    // 0..3

    const int b  = blockIdx.y;
    const int q0 = blockIdx.x * BQ;

    const float escale = (1.0f / scale_div[0]) * 1.44269504088896340736f;

    // prologue: start tile-0 copy before the Q work
    issue_planes(&g_KB[b][0][0][0], &g_VP[b][0][0][0], KB0, VP0, tid);

    // ---- Q fragments: bf16 hi/lo split once into registers ----
    const int rA = q0 + w * 16 + g;
    const int rB = rA + 8;
    const float* Qa = Q + ((size_t)b * SQ_ + rA) * D_;
    const float* Qb = Q + ((size_t)b * SQ_ + rB) * D_;
    uint32_t qhi[4][4], qlo[4][4];
    #pragma unroll
    for (int s = 0; s < 4; ++s) {
        float2 pa = __ldg(reinterpret_cast<const float2*>(Qa + 16 * s + 2 * tg));
        float2 pb = __ldg(reinterpret_cast<const float2*>(Qb + 16 * s + 2 * tg));
        float2 pc = __ldg(reinterpret_cast<const float2*>(Qa + 16 * s + 8 + 2 * tg));
        float2 pd = __ldg(reinterpret_cast<const float2*>(Qb + 16 * s + 8 + 2 * tg));
        float r0, r1;
        qhi[s][0] = pack_bf16_hi(pa.x, pa.y, r0, r1); qlo[s][0] = pack_bf16(r0, r1);
        qhi[s][1] = pack_bf16_hi(pb.x, pb.y, r0, r1); qlo[s][1] = pack_bf16(r0, r1);
        qhi[s][2] = pack_bf16_hi(pc.x, pc.y, r0, r1); qlo[s][2] = pack_bf16(r0, r1);
        qhi[s][3] = pack_bf16_hi(pd.x, pd.y, r0, r1); qlo[s][3] = pack_bf16(r0, r1);
    }

    float o[8][4];
    #pragma unroll
    for (int nt = 0; nt < 8; ++nt)
        #pragma unroll
        for (int j = 0; j < 4; ++j) o[nt][j] = 0.0f;

    float mA = -INFINITY, mB = -INFINITY;
    float lA = 0.0f, lB = 0.0f;
    float aAp = 1.0f, aBp = 1.0f;    // alpha of the previous tile (for deferred l update)
    uint32_t xpk[4][4];              // packed fp16x2 exp2-arguments of the previous tile

    // tile-0 planes ready
    asm volatile("cp.async.wait_group 0;");
    __syncthreads();

    for (int t = 0; t < NT_; ++t) {
        const uint32_t* KBt = KB0 + (t & 1) * KB_U32;

        // issue next tile's copy (kb[(t+1)&1] free since QK(t-1); vb[(t+1)%3]
        // free since PV(t-2) — both pre-barrier in earlier iterations)
        if (t + 1 < NT_)
            issue_planes(&g_KB[b][t + 1][0][0], &g_VP[b][t + 1][0][0],
                         KB0 + ((t + 1) & 1) * KB_U32,
                         VP0 + ((t + 1) % 3) * V_U32, tid);

        // ---- S = Q K^T via bf16x3 (hh + hl + lh) ----
        float sc[8][4];
        #pragma unroll
        for (int nt = 0; nt < 8; ++nt)
            #pragma unroll
            for (int j = 0; j < 4; ++j) sc[nt][j] = 0.0f;

        #pragma unroll
        for (int s = 0; s < 4; ++s) {
            #pragma unroll
            for (int nt = 0; nt < 8; ++nt) {
                const uint32_t* krow = KBt + (nt * 8 + g) * KBSTRIDE + 8 * s + 2 * tg;
                uint2 bh = *reinterpret_cast<const uint2*>(krow);
                uint2 bl = *reinterpret_cast<const uint2*>(krow + 32);
                mma_bf16(sc[nt][0], sc[nt][1], sc[nt][2], sc[nt][3],
                         qhi[s][0], qhi[s][1], qhi[s][2], qhi[s][3], bh.x, bh.y);
                mma_bf16(sc[nt][0], sc[nt][1], sc[nt][2], sc[nt][3],
                         qhi[s][0], qhi[s][1], qhi[s][2], qhi[s][3], bl.x, bl.y);
                mma_bf16(sc[nt][0], sc[nt][1], sc[nt][2], sc[nt][3],
                         qlo[s][0], qlo[s][1], qlo[s][2], qlo[s][3], bh.x, bh.y);
            }
        }

        // ---- DEFERRED PV of tile t-1 (independent of QK(t) results; keeps the
        //      tensor pipe fed while QK(t) completes) ----
        if (t > 0) {
            const uint32_t* VPp = VP0 + ((t - 1) % 3) * V_U32;
            float la0 = 0.0f, la1 = 0.0f, la2 = 0.0f, la3 = 0.0f;
            #pragma unroll
            for (int s = 0; s < 4; ++s) {
                uint32_t a0 = exp2_f16x2(xpk[s][0]);
                uint32_t a1 = exp2_f16x2(xpk[s][1]);
                uint32_t a2 = exp2_f16x2(xpk[s][2]);
                uint32_t a3 = exp2_f16x2(xpk[s][3]);
                mma_f16(la0, la1, la2, la3, a0, a1, a2, a3, ONES_F16X2, ONES_F16X2);
                #pragma unroll
                for (int nt = 0; nt < 8; ++nt) {
                    uint2 vv = *reinterpret_cast<const uint2*>(
                        VPp + (nt * 8 + g) * VSTRIDE + 8 * s + 2 * tg);
                    mma_f16(o[nt][0], o[nt][1], o[nt][2], o[nt][3],
                            a0, a1, a2, a3, vv.x, vv.y);
                }
            }
            lA = fmaf(lA, aAp, la0);
            lB = fmaf(lB, aBp, la2);
        }

        // ---- softmax-part1(t): max, rescale o, pack exp2-arguments ----
        float rmA = -INFINITY, rmB = -INFINITY;
        #pragma unroll
        for (int nt = 0; nt < 8; ++nt) {
            rmA = fmaxf(rmA, fmaxf(sc[nt][0], sc[nt][1]));
            rmB = fmaxf(rmB, fmaxf(sc[nt][2], sc[nt][3]));
        }
        rmA = fmaxf(rmA, __shfl_xor_sync(0xffffffffu, rmA, 1));
        rmA = fmaxf(rmA, __shfl_xor_sync(0xffffffffu, rmA, 2));
        rmB = fmaxf(rmB, __shfl_xor_sync(0xffffffffu, rmB, 1));
        rmB = fmaxf(rmB, __shfl_xor_sync(0xffffffffu, rmB, 2));

        const float mAn = fmaxf(mA, rmA * escale);
        const float mBn = fmaxf(mB, rmB * escale);
        const float aA = fast_exp2(mA - mAn);
        const float aB = fast_exp2(mB - mBn);
        mA = mAn; mB = mBn;
        #pragma unroll
        for (int nt = 0; nt < 8; ++nt) {
            o[nt][0] *= aA; o[nt][1] *= aA;
            o[nt][2] *= aB; o[nt][3] *= aB;
        }
        #pragma unroll
        for (int s = 0; s < 4; ++s) {
            xpk[s][0] = pack_f16(fmaf(sc[2*s][0],   escale, -mA),
                                 fmaf(sc[2*s][1],   escale, -mA));
            xpk[s][1] = pack_f16(fmaf(sc[2*s][2],   escale, -mB),
                                 fmaf(sc[2*s][3],   escale, -mB));
            xpk[s][2] = pack_f16(fmaf(sc[2*s+1][0], escale, -mA),
                                 fmaf(sc[2*s+1][1], escale, -mA));
            xpk[s][3] = pack_f16(fmaf(sc[2*s+1][2], escale, -mB),
                                 fmaf(sc[2*s+1][3], escale, -mB));
        }
        aAp = aA; aBp = aB;

        // ---- tile end: next planes arrived; single barrier publishes them ----
        if (t + 1 < NT_) {
            asm volatile("cp.async.wait_group 0;");
            __syncthreads();
        }
    }

    // ---- epilogue: last deferred PV (tile NT-1), then normalize + store ----
    {
        const uint32_t* VPp = VP0 + ((NT_ - 1) % 3) * V_U32;
        float la0 = 0.0f, la1 = 0.0f, la2 = 0.0f, la3 = 0.0f;
        #pragma unroll
        for (int s = 0; s < 4; ++s) {
            uint32_t a0 = exp2_f16x2(xpk[s][0]);
            uint32_t a1 = exp2_f16x2(xpk[s][1]);
            uint32_t a2 = exp2_f16x2(xpk[s][2]);
            uint32_t a3 = exp2_f16x2(xpk[s][3]);
            mma_f16(la0, la1, la2, la3, a0, a1, a2, a3, ONES_F16X2, ONES_F16X2);
            #pragma unroll
            for (int nt = 0; nt < 8; ++nt) {
                uint2 vv = *reinterpret_cast<const uint2*>(
                    VPp + (nt * 8 + g) * VSTRIDE + 8 * s + 2 * tg);
                mma_f16(o[nt][0], o[nt][1], o[nt][2], o[nt][3],
                        a0, a1, a2, a3, vv.x, vv.y);
            }
        }
        lA = fmaf(lA, aAp, la0);
        lB = fmaf(lB, aBp, la2);
    }

    const float iA = 1.0f / lA;
    const float iB = 1.0f / lB;

    float* Oa = O + ((size_t)b * SQ_ + rA) * D_;
    float* Ob = O + ((size_t)b * SQ_ + rB) * D_;
    #pragma unroll
    for (int nt = 0; nt < 8; ++nt) {
        *reinterpret_cast<float2*>(Oa + nt * 8 + 2 * tg)
            = make_float2(o[nt][0] * iA, o[nt][1] * iA);
        *reinterpret_cast<float2*>(Ob + nt * 8 + 2 * tg)
            = make_float2(o[nt][2] * iB, o[nt][3] * iB);
    }
}

extern "C" void kernel_launch(void* const* d_in, const int* in_sizes, int n_in,
                              void* d_out, int out_size) {
    const float* Q = (const float*)d_in[0];
    const float* K = (const float*)d_in[1];
    const float* V = (const float*)d_in[2];
    const float* s = (const float*)d_in[n_in - 1];
    float* O = (float*)d_out;

    dim3 pgrid(NT_, B_);
    fa_preconv_kernel<<<pgrid, 256>>>(K, V);

    cudaFuncSetAttribute(fa_main_kernel,
                         cudaFuncAttributeMaxDynamicSharedMemorySize, SMEM_BYTES);
    dim3 grid(SQ_ / BQ, B_);
    fa_main_kernel<<<grid, NTHREADS, SMEM_BYTES>>>(Q, s, O);
}

// round 16
// speedup vs baseline: 1.0434x; 1.0434x over previous
#include <cuda_runtime.h>
#include <cstdint>
#include <math.h>

// Problem constants (B=8, SQ=SK=4096, D=64)
#define B_   8
#define SQ_  4096
#define SK_  4096
#define D_   64

#define BQ   128
#define BK   64
#define NT_  (SK_ / BK)   // 64 tiles
#define NTHREADS 256
#define KBSTRIDE  80      // K plane smem row stride (u32; 320B rows -> LDS.128 conflict-free)
#define VSTRIDE   40      // V fp16 plane smem dim-row stride (u32)

#define KB_U32      (BK * KBSTRIDE)               // 5120 per buffer
#define V_U32       (D_ * VSTRIDE)                // 2560 per buffer
#define SMEM_U32    (2 * KB_U32 + 2 * V_U32)      // 15360
#define SMEM_BYTES  (SMEM_U32 * 4)                // 61440 -> 2 CTAs/SM

#define ONES_F16X2  0x3C003C00u                   // fp16 {1.0, 1.0}

// pre-converted K/V planes. K row layout (64 u32): for dim-chunk s (0..3),
// tg (0..3): group of 4 u32 at s*16+tg*4 = [bh0, bh1, bl0, bl1] — the complete
// hi+lo B-fragment for (s, tg), fetched by ONE LDS.128 in the main kernel.
__device__ uint32_t g_KB[B_][NT_][BK][64];   // 8 MB
__device__ uint32_t g_VP[B_][NT_][D_][32];   // 4 MB

__device__ __forceinline__ float fast_exp2(float x) {
    float y; asm("ex2.approx.ftz.f32 %0, %1;" : "=f"(y) : "f"(x)); return y;
}
__device__ __forceinline__ uint32_t exp2_f16x2(uint32_t x) {
    uint32_t y; asm("ex2.approx.f16x2 %0, %1;" : "=r"(y) : "r"(x)); return y;
}
__device__ __forceinline__ uint32_t pack_bf16_hi(float f0, float f1, float& r0, float& r1) {
    uint32_t u;
    asm("cvt.rn.bf16x2.f32 %0, %1, %2;" : "=r"(u) : "f"(f1), "f"(f0));
    r0 = f0 - __uint_as_float(u << 16);
    r1 = f1 - __uint_as_float(u & 0xffff0000u);
    return u;
}
__device__ __forceinline__ uint32_t pack_bf16(float f0, float f1) {
    uint32_t u;
    asm("cvt.rn.bf16x2.f32 %0, %1, %2;" : "=r"(u) : "f"(f1), "f"(f0));
    return u;
}
__device__ __forceinline__ uint32_t pack_f16(float f0, float f1) {
    uint32_t u;
    asm("cvt.rn.f16x2.f32 %0, %1, %2;" : "=r"(u) : "f"(f1), "f"(f0));
    return u;
}

__device__ __forceinline__ void mma_bf16(float& d0, float& d1, float& d2, float& d3,
                                         uint32_t a0, uint32_t a1, uint32_t a2, uint32_t a3,
                                         uint32_t b0, uint32_t b1) {
    asm volatile(
        "mma.sync.aligned.m16n8k16.row.col.f32.bf16.bf16.f32 "
        "{%0,%1,%2,%3}, {%4,%5,%6,%7}, {%8,%9}, {%0,%1,%2,%3};"
        : "+f"(d0), "+f"(d1), "+f"(d2), "+f"(d3)
        : "r"(a0), "r"(a1), "r"(a2), "r"(a3), "r"(b0), "r"(b1));
}
__device__ __forceinline__ void mma_f16(float& d0, float& d1, float& d2, float& d3,
                                        uint32_t a0, uint32_t a1, uint32_t a2, uint32_t a3,
                                        uint32_t b0, uint32_t b1) {
    asm volatile(
        "mma.sync.aligned.m16n8k16.row.col.f32.f16.f16.f32 "
        "{%0,%1,%2,%3}, {%4,%5,%6,%7}, {%8,%9}, {%0,%1,%2,%3};"
        : "+f"(d0), "+f"(d1), "+f"(d2), "+f"(d3)
        : "r"(a0), "r"(a1), "r"(a2), "r"(a3), "r"(b0), "r"(b1));
}

__device__ __forceinline__ void cp_async16(uint32_t dst, const void* src) {
    asm volatile("cp.async.cg.shared.global [%0], [%1], 16;" :: "r"(dst), "l"(src));
}

// ================= pre-pass: fp32 K/V -> packed planes (gmem) =================
__global__ void __launch_bounds__(256)
fa_preconv_kernel(const float* __restrict__ K, const float* __restrict__ V)
{
    const int tile = blockIdx.x;
    const int b    = blockIdx.y;
    const int tid  = threadIdx.x;

    // ---- K: thread = (key row, 16-dim chunk); interleaved [bh0,bh1,bl0,bl1] ----
    {
        const int kkey = tid >> 2, kdc = tid & 3;
        const float* ksrc = K + (((size_t)b * SK_) + tile * BK + kkey) * D_ + kdc * 16;
        float4 v0 = __ldg(reinterpret_cast<const float4*>(ksrc));
        float4 v1 = __ldg(reinterpret_cast<const float4*>(ksrc + 4));
        float4 v2 = __ldg(reinterpret_cast<const float4*>(ksrc + 8));
        float4 v3 = __ldg(reinterpret_cast<const float4*>(ksrc + 12));
        float r[16];
        uint32_t hi[8], lo[8];
        hi[0] = pack_bf16_hi(v0.x, v0.y, r[0], r[1]);
        hi[1] = pack_bf16_hi(v0.z, v0.w, r[2], r[3]);
        hi[2] = pack_bf16_hi(v1.x, v1.y, r[4], r[5]);
        hi[3] = pack_bf16_hi(v1.z, v1.w, r[6], r[7]);
        hi[4] = pack_bf16_hi(v2.x, v2.y, r[8], r[9]);
        hi[5] = pack_bf16_hi(v2.z, v2.w, r[10], r[11]);
        hi[6] = pack_bf16_hi(v3.x, v3.y, r[12], r[13]);
        hi[7] = pack_bf16_hi(v3.z, v3.w, r[14], r[15]);
        #pragma unroll
        for (int j = 0; j < 8; ++j) lo[j] = pack_bf16(r[2 * j], r[2 * j + 1]);
        uint32_t* kdst = &g_KB[b][tile][kkey][kdc * 16];
        *reinterpret_cast<uint4*>(kdst)      = make_uint4(hi[0], hi[4], lo[0], lo[4]);
        *reinterpret_cast<uint4*>(kdst + 4)  = make_uint4(hi[1], hi[5], lo[1], lo[5]);
        *reinterpret_cast<uint4*>(kdst + 8)  = make_uint4(hi[2], hi[6], lo[2], lo[6]);
        *reinterpret_cast<uint4*>(kdst + 12) = make_uint4(hi[3], hi[7], lo[3], lo[7]);
    }
    // ---- V: thread = (key pair, 8-dim chunk), column-permuted fp16 ----
    {
        const int vkp = tid & 31, vdc = tid >> 5;
        const int vcol = (vkp & 24) | ((vkp & 3) << 1) | ((vkp >> 2) & 1);
        const float* s0 = V + (((size_t)b * SK_) + tile * BK + 2 * vkp) * D_ + vdc * 8;
        const float* s1 = s0 + D_;
        #pragma unroll
        for (int i = 0; i < 2; ++i) {
            float4 a = __ldg(reinterpret_cast<const float4*>(s0 + 4 * i));
            float4 c = __ldg(reinterpret_cast<const float4*>(s1 + 4 * i));
            float fa[4] = {a.x, a.y, a.z, a.w};
            float fc[4] = {c.x, c.y, c.z, c.w};
            #pragma unroll
            for (int j = 0; j < 4; ++j) {
                int d = vdc * 8 + 4 * i + j;
                g_VP[b][tile][d][vcol] = pack_f16(fa[j], fc[j]);
            }
        }
    }
}

// cp.async one tile's planes into smem buffers (256 threads).
// K: 64 rows x 256B (src stride 64 u32, dst stride KBSTRIDE=80).
// V: 64 rows x 128B (src stride 32 u32, dst stride VSTRIDE=40).
__device__ __forceinline__ void issue_planes(const uint32_t* __restrict__ KBg,
                                             const uint32_t* __restrict__ VPg,
                                             uint32_t* KBs, uint32_t* VPs, int tid) {
    #pragma unroll
    for (int i = 0; i < 4; ++i) {
        int slot = tid + i * NTHREADS;      // 1024 chunks of 16B
        int row = slot >> 4, c = slot & 15;
        uint32_t dst = (uint32_t)__cvta_generic_to_shared(KBs + row * KBSTRIDE + c * 4);
        cp_async16(dst, KBg + row * 64 + c * 4);
    }
    #pragma unroll
    for (int i = 0; i < 2; ++i) {
        int slot = tid + i * NTHREADS;      // 512 chunks of 16B
        int row = slot >> 3, c = slot & 7;
        uint32_t dst = (uint32_t)__cvta_generic_to_shared(VPs + row * VSTRIDE + c * 4);
        cp_async16(dst, VPg + row * 32 + c * 4);
    }
    asm volatile("cp.async.commit_group;");
}

__global__ void __launch_bounds__(NTHREADS, 2)
fa_main_kernel(const float* __restrict__ Q, const float* __restrict__ scale_div,
               float* __restrict__ O)
{
    extern __shared__ uint32_t smem[];
    uint32_t* KB0 = smem;                    // double-buffered K planes
    uint32_t* VP0 = smem + 2 * KB_U32;       // double-buffered V planes

    const int tid  = threadIdx.x;
    const int w    = tid >> 5;
    const int lane = tid & 31;
    const int g    = lane >> 2;   // 0..7
    const int tg   = lane & 3;    // 0..3

    const int b  = blockIdx.y;
    const int q0 = blockIdx.x * BQ;

    const float escale = (1.0f / scale_div[0]) * 1.44269504088896340736f;

    // prologue: start tile-0 copy before the Q work
    issue_planes(&g_KB[b][0][0][0], &g_VP[b][0][0][0], KB0, VP0, tid);

    // ---- Q fragments: bf16 hi/lo split once into registers ----
    const int rA = q0 + w * 16 + g;
    const int rB = rA + 8;
    const float* Qa = Q + ((size_t)b * SQ_ + rA) * D_;
    const float* Qb = Q + ((size_t)b * SQ_ + rB) * D_;
    uint32_t qhi[4][4], qlo[4][4];
    #pragma unroll
    for (int s = 0; s < 4; ++s) {
        float2 pa = __ldg(reinterpret_cast<const float2*>(Qa + 16 * s + 2 * tg));
        float2 pb = __ldg(reinterpret_cast<const float2*>(Qb + 16 * s + 2 * tg));
        float2 pc = __ldg(reinterpret_cast<const float2*>(Qa + 16 * s + 8 + 2 * tg));
        float2 pd = __ldg(reinterpret_cast<const float2*>(Qb + 16 * s + 8 + 2 * tg));
        float r0, r1;
        qhi[s][0] = pack_bf16_hi(pa.x, pa.y, r0, r1); qlo[s][0] = pack_bf16(r0, r1);
        qhi[s][1] = pack_bf16_hi(pb.x, pb.y, r0, r1); qlo[s][1] = pack_bf16(r0, r1);
        qhi[s][2] = pack_bf16_hi(pc.x, pc.y, r0, r1); qlo[s][2] = pack_bf16(r0, r1);
        qhi[s][3] = pack_bf16_hi(pd.x, pd.y, r0, r1); qlo[s][3] = pack_bf16(r0, r1);
    }

    float o[8][4];
    #pragma unroll
    for (int nt = 0; nt < 8; ++nt)
        #pragma unroll
        for (int j = 0; j < 4; ++j) o[nt][j] = 0.0f;

    float mA = -INFINITY, mB = -INFINITY;
    float lA = 0.0f, lB = 0.0f;

    // tile-0 planes ready
    asm volatile("cp.async.wait_group 0;");
    __syncthreads();

    for (int t = 0; t < NT_; ++t) {
        const uint32_t* KBt = KB0 + (t & 1) * KB_U32;
        const uint32_t* VPt = VP0 + (t & 1) * V_U32;

        // issue next tile's copy into the other buffer; waited at tile end.
        if (t + 1 < NT_)
            issue_planes(&g_KB[b][t + 1][0][0], &g_VP[b][t + 1][0][0],
                         KB0 + ((t + 1) & 1) * KB_U32, VP0 + ((t + 1) & 1) * V_U32, tid);

        // ---- S = Q K^T via bf16x3. Loads hoisted in groups of 4 fragments
        //      (one LDS.128 per fragment: hi+lo together) so the crossbar
        //      time of group i+1 hides under the MMAs of group i. ----
        float sc[8][4];
        #pragma unroll
        for (int nt = 0; nt < 8; ++nt)
            #pragma unroll
            for (int j = 0; j < 4; ++j) sc[nt][j] = 0.0f;

        #pragma unroll
        for (int s = 0; s < 4; ++s) {
            #pragma unroll
            for (int h = 0; h < 2; ++h) {
                uint4 kv[4];
                #pragma unroll
                for (int i = 0; i < 4; ++i)
                    kv[i] = *reinterpret_cast<const uint4*>(
                        KBt + ((h * 4 + i) * 8 + g) * KBSTRIDE + s * 16 + tg * 4);
                #pragma unroll
                for (int i = 0; i < 4; ++i) {
                    const int nt = h * 4 + i;
                    mma_bf16(sc[nt][0], sc[nt][1], sc[nt][2], sc[nt][3],
                             qhi[s][0], qhi[s][1], qhi[s][2], qhi[s][3], kv[i].x, kv[i].y);
                    mma_bf16(sc[nt][0], sc[nt][1], sc[nt][2], sc[nt][3],
                             qhi[s][0], qhi[s][1], qhi[s][2], qhi[s][3], kv[i].z, kv[i].w);
                    mma_bf16(sc[nt][0], sc[nt][1], sc[nt][2], sc[nt][3],
                             qlo[s][0], qlo[s][1], qlo[s][2], qlo[s][3], kv[i].x, kv[i].y);
                }
            }
        }

        // ---- running max (raw scores), rescale o ----
        float rmA = -INFINITY, rmB = -INFINITY;
        #pragma unroll
        for (int nt = 0; nt < 8; ++nt) {
            rmA = fmaxf(rmA, fmaxf(sc[nt][0], sc[nt][1]));
            rmB = fmaxf(rmB, fmaxf(sc[nt][2], sc[nt][3]));
        }
        rmA = fmaxf(rmA, __shfl_xor_sync(0xffffffffu, rmA, 1));
        rmA = fmaxf(rmA, __shfl_xor_sync(0xffffffffu, rmA, 2));
        rmB = fmaxf(rmB, __shfl_xor_sync(0xffffffffu, rmB, 1));
        rmB = fmaxf(rmB, __shfl_xor_sync(0xffffffffu, rmB, 2));

        const float mAn = fmaxf(mA, rmA * escale);
        const float mBn = fmaxf(mB, rmB * escale);
        const float aA = fast_exp2(mA - mAn);
        const float aB = fast_exp2(mB - mBn);
        mA = mAn; mB = mBn;
        #pragma unroll
        for (int nt = 0; nt < 8; ++nt) {
            o[nt][0] *= aA; o[nt][1] *= aA;
            o[nt][2] *= aB; o[nt][3] *= aB;
        }

        // ---- per s-step: x -> packed f16x2 -> ex2.f16x2 -> l-MMA + PV
        //      (V loads hoisted in groups of 4) ----
        float la0 = 0.0f, la1 = 0.0f, la2 = 0.0f, la3 = 0.0f;
        #pragma unroll
        for (int s = 0; s < 4; ++s) {
            float x0 = fmaf(sc[2*s][0],   escale, -mA);
            float x1 = fmaf(sc[2*s][1],   escale, -mA);
            float x2 = fmaf(sc[2*s][2],   escale, -mB);
            float x3 = fmaf(sc[2*s][3],   escale, -mB);
            float x4 = fmaf(sc[2*s+1][0], escale, -mA);
            float x5 = fmaf(sc[2*s+1][1], escale, -mA);
            float x6 = fmaf(sc[2*s+1][2], escale, -mB);
            float x7 = fmaf(sc[2*s+1][3], escale, -mB);
            uint32_t a0 = exp2_f16x2(pack_f16(x0, x1));
            uint32_t a1 = exp2_f16x2(pack_f16(x2, x3));
            uint32_t a2 = exp2_f16x2(pack_f16(x4, x5));
            uint32_t a3 = exp2_f16x2(pack_f16(x6, x7));
            mma_f16(la0, la1, la2, la3, a0, a1, a2, a3, ONES_F16X2, ONES_F16X2);
            #pragma unroll
            for (int h = 0; h < 2; ++h) {
                uint2 vv[4];
                #pragma unroll
                for (int i = 0; i < 4; ++i)
                    vv[i] = *reinterpret_cast<const uint2*>(
                        VPt + ((h * 4 + i) * 8 + g) * VSTRIDE + 8 * s + 2 * tg);
                #pragma unroll
                for (int i = 0; i < 4; ++i) {
                    const int nt = h * 4 + i;
                    mma_f16(o[nt][0], o[nt][1], o[nt][2], o[nt][3],
                            a0, a1, a2, a3, vv[i].x, vv[i].y);
                }
            }
        }
        lA = fmaf(lA, aA, la0);
        lB = fmaf(lB, aB, la2);

        // ---- tile end: next tile's planes arrived; single barrier publishes ----
        if (t + 1 < NT_) {
            asm volatile("cp.async.wait_group 0;");
            __syncthreads();
        }
    }

    // ---- epilogue: l is a full row sum (l-MMA) -> normalize, store ----
    const float iA = 1.0f / lA;
    const float iB = 1.0f / lB;

    float* Oa = O + ((size_t)b * SQ_ + rA) * D_;
    float* Ob = O + ((size_t)b * SQ_ + rB) * D_;
    #pragma unroll
    for (int nt = 0; nt < 8; ++nt) {
        *reinterpret_cast<float2*>(Oa + nt * 8 + 2 * tg)
            = make_float2(o[nt][0] * iA, o[nt][1] * iA);
        *reinterpret_cast<float2*>(Ob + nt * 8 + 2 * tg)
            = make_float2(o[nt][2] * iB, o[nt][3] * iB);
    }
}

extern "C" void kernel_launch(void* const* d_in, const int* in_sizes, int n_in,
                              void* d_out, int out_size) {
    const float* Q = (const float*)d_in[0];
    const float* K = (const float*)d_in[1];
    const float* V = (const float*)d_in[2];
    const float* s = (const float*)d_in[n_in - 1];
    float* O = (float*)d_out;

    dim3 pgrid(NT_, B_);
    fa_preconv_kernel<<<pgrid, 256>>>(K, V);

    cudaFuncSetAttribute(fa_main_kernel,
                         cudaFuncAttributeMaxDynamicSharedMemorySize, SMEM_BYTES);
    dim3 grid(SQ_ / BQ, B_);
    fa_main_kernel<<<grid, NTHREADS, SMEM_BYTES>>>(Q, s, O);
}